// round 15
// baseline (speedup 1.0000x reference)
#include <cuda_runtime.h>
#include <cuda_bf16.h>
#include <math.h>

#define H 1024
#define W 1024
#define OROWS 4                       // output rows per CTA
#define FHALO 3                       // fast-path window radius
#define SROWS (OROWS + 2 * FHALO)     // 10 scan rows per CTA
#define NTASK (SROWS * 2)             // 20 half-row tasks per CTA
#define SMEM_BYTES (SROWS * W * sizeof(float))   // 40 KB dynamic

__device__ __forceinline__ float sqrt_approx(float x) {
    float r;
    asm("sqrt.approx.f32 %0, %1;" : "=f"(r) : "f"(x));
    return r;
}

// Exact fallback: brute force over all zero pixels. Correct for any input;
// fires with probability ~2e-9 per pixel (all 7 fast-window rows jointly bad).
__device__ __noinline__ float brute_force_d2(const float* __restrict__ img,
                                             int i, int j) {
    float best = 3.4e38f;
    for (int p = 0; p < H; p++) {
        const float dp = (float)(i - p);
        const float dp2 = dp * dp;
        if (dp2 >= best) continue;
        for (int q = 0; q < W; q++) {
            if (img[p * W + q] == 0.0f) {
                const float dq = (float)(j - q);
                best = fminf(best, dp2 + dq * dq);
            }
        }
    }
    if (best > 1e10f) best = 1e10f;   // no zero anywhere -> reference BIG
    return best;
}

// ---------------------------------------------------------------------------
// Fused EDT, clamped-local row pass, sized for multi-CTA residency.
// Phase A: 20 half-row tasks (10 rows x 2 halves, 16 px/lane). Row distance
// CLAMPED to 3 (d^2 in {0,1,4,9,16} as float): per pixel just a 7-bit window
// of the zero mask -> no scans, no carries.
// Phase B: 2 columns/thread, 7-tap parabola min over +-3 rows; m<=9 is
// provably the exact global min, else exact brute-force fallback.
// ---------------------------------------------------------------------------
__global__ void __launch_bounds__(512) edt_fused_kernel(
    const float* __restrict__ img, float* __restrict__ out) {

    extern __shared__ float sd[];             // [SROWS][W], 40 KB dynamic
    __shared__ unsigned eb_lo[SROWS][2];      // first-3-px zero bits per half
    __shared__ unsigned eb_hi[SROWS][2];      // last-3-px zero bits per half

    const int tid = threadIdx.x;
    const int lane = tid & 31;
    const int wid = tid >> 5;                 // 0..15
    const int ob = blockIdx.x * OROWS;        // first output row of this CTA

    // -------- Phase A, step 1: load pixels, build 16-bit zero masks --------
    unsigned msk[2];
    int rownum[2], hnum[2], basepx[2];
    #pragma unroll
    for (int s = 0; s < 2; s++) {
        const int t = wid + s * 16;
        if (t < NTASK) {
            const int r = t >> 1;             // scan row 0..9
            const int hh = t & 1;             // half 0..1
            const int base = hh * 512 + lane * 16;
            const int srow = ob - FHALO + r;  // global image row
            unsigned mk = 0u;
            if (srow >= 0 && srow < H) {
                const float4* __restrict__ i4 =
                    (const float4*)(img + srow * W) + base / 4;
                #pragma unroll
                for (int q = 0; q < 4; q++) {
                    const float4 v = i4[q];
                    if (v.x == 0.0f) mk |= 1u << (q * 4 + 0);
                    if (v.y == 0.0f) mk |= 1u << (q * 4 + 1);
                    if (v.z == 0.0f) mk |= 1u << (q * 4 + 2);
                    if (v.w == 0.0f) mk |= 1u << (q * 4 + 3);
                }
            }
            msk[s] = mk;
            rownum[s] = r; hnum[s] = hh; basepx[s] = base;
            if (lane == 0)  eb_lo[r][hh] = mk & 7u;
            if (lane == 31) eb_hi[r][hh] = mk >> 13;
        } else {
            rownum[s] = -1; msk[s] = 0u; hnum[s] = 0; basepx[s] = 0;
        }
    }
    __syncthreads();

    // -------- Phase A, step 2: per-pixel clamped distance (7-bit window) ---
    #pragma unroll
    for (int s = 0; s < 2; s++) {
        if (rownum[s] >= 0) {                 // warp-uniform branch
            const unsigned mk = msk[s];
            const int r = rownum[s], hh = hnum[s], base = basepx[s];

            unsigned p3 = __shfl_up_sync(0xffffffffu, mk, 1) >> 13;
            if (lane == 0) p3 = hh ? eb_hi[r][0] : 0u;
            unsigned n3 = __shfl_down_sync(0xffffffffu, mk, 1) & 7u;
            if (lane == 31) n3 = hh ? 0u : eb_lo[r][1];

            // ext bit k = zero flag of pixel (base - 3 + k), k = 0..21
            const unsigned ext = p3 | (mk << 3) | (n3 << 19);

            float dv[16];
            #pragma unroll
            for (int p = 0; p < 16; p++) {
                const unsigned wb = (ext >> p) & 0x7Fu;  // bit 3 = center px
                float d2 = 16.0f;                        // d >= 4 (clamped)
                if (wb & 0x41u) d2 = 9.0f;               // d = 3
                if (wb & 0x22u) d2 = 4.0f;               // d = 2
                if (wb & 0x14u) d2 = 1.0f;               // d = 1
                if (wb & 0x08u) d2 = 0.0f;               // d = 0
                dv[p] = d2;
            }
            #pragma unroll
            for (int q = 0; q < 4; q++) {
                *(float4*)&sd[r * W + base + q * 4] =
                    make_float4(dv[q * 4], dv[q * 4 + 1], dv[q * 4 + 2], dv[q * 4 + 3]);
            }
        }
    }
    __syncthreads();

    // -------- Phase B: column parabola window (2 columns per thread) -------
    const int j0 = tid * 2;

    float wl[SROWS], wr[SROWS];
    #pragma unroll
    for (int k = 0; k < SROWS; k++) {
        const float2 v = *(const float2*)&sd[k * W + j0];
        wl[k] = v.x;
        wr[k] = v.y;
    }

    float ml[OROWS], mr[OROWS];
    #pragma unroll
    for (int u = 0; u < OROWS; u++) {
        ml[u] = wl[u + FHALO];                // d_i = 0 tap
        mr[u] = wr[u + FHALO];
    }
    #pragma unroll
    for (int d = 1; d <= FHALO; d++) {
        const float dd = (float)(d * d);
        #pragma unroll
        for (int u = 0; u < OROWS; u++) {
            ml[u] = fminf(ml[u], wl[u + FHALO - d] + dd);
            ml[u] = fminf(ml[u], wl[u + FHALO + d] + dd);
            mr[u] = fminf(mr[u], wr[u + FHALO - d] + dd);
            mr[u] = fminf(mr[u], wr[u + FHALO + d] + dd);
        }
    }

    // m <= 9 => exact: clamped taps and |d_i| >= 4 taps are all >= 16 > 9.
    #pragma unroll
    for (int u = 0; u < OROWS; u++) {
        float a = ml[u], b = mr[u];
        if (a > 9.0f) a = brute_force_d2(img, ob + u, j0);
        if (b > 9.0f) b = brute_force_d2(img, ob + u, j0 + 1);
        *(float2*)(out + (ob + u) * W + j0) =
            make_float2(sqrt_approx(a), sqrt_approx(b));
    }
}

// ---------------------------------------------------------------------------
extern "C" void kernel_launch(void* const* d_in, const int* in_sizes, int n_in,
                              void* d_out, int out_size) {
    const float* img = (const float*)d_in[0];
    float* out = (float*)d_out;

    // Deterministic, capture-safe (not a stream op, no allocation).
    cudaFuncSetAttribute(edt_fused_kernel,
                         cudaFuncAttributeMaxDynamicSharedMemorySize,
                         (int)SMEM_BYTES);

    edt_fused_kernel<<<H / OROWS, 512, SMEM_BYTES>>>(img, out);  // 256 CTAs
}

// round 16
// speedup vs baseline: 1.1429x; 1.1429x over previous
#include <cuda_runtime.h>
#include <cuda_bf16.h>
#include <math.h>

#define H 1024
#define W 1024
#define CW 256                        // columns per CTA
#define OROWS 8                       // output rows per CTA
#define FHALO 3                       // fast-path window radius
#define SROWS (OROWS + 2 * FHALO)     // 14 scan rows per CTA

__device__ __forceinline__ float sqrt_approx(float x) {
    float r;
    asm("sqrt.approx.f32 %0, %1;" : "=f"(r) : "f"(x));
    return r;
}

// Exact fallback: brute force over all zero pixels. Correct for any input;
// fires with probability ~2e-9 per pixel (all 7 fast-window rows jointly bad).
__device__ __noinline__ float brute_force_d2(const float* __restrict__ img,
                                             int i, int j) {
    float best = 3.4e38f;
    for (int p = 0; p < H; p++) {
        const float dp = (float)(i - p);
        const float dp2 = dp * dp;
        if (dp2 >= best) continue;
        for (int q = 0; q < W; q++) {
            if (img[p * W + q] == 0.0f) {
                const float dq = (float)(j - q);
                best = fminf(best, dp2 + dq * dq);
            }
        }
    }
    if (best > 1e10f) best = 1e10f;   // no zero anywhere -> reference BIG
    return best;
}

// ---------------------------------------------------------------------------
// Fused EDT, fully 2D-tiled (clamped row pass is LOCAL: +-3 px only).
// CTA = 256 cols x 8 output rows. Phase A: warp per scan-row segment,
// 8 px/lane, 7-bit-window clamped d^2 into 14KB smem; column halo bits via
// shfl + <=3 scalar gmem loads at segment edges. Phase B: 1 col/thread,
// 7-tap parabola min; m<=9 provably exact, else brute-force fallback.
// 512 CTAs x 256 thr, ~14KB smem -> entire grid resident in one wave.
// ---------------------------------------------------------------------------
__global__ void __launch_bounds__(256) edt_fused_kernel(
    const float* __restrict__ img, float* __restrict__ out) {

    __shared__ float sd[SROWS * CW];          // 14 KB clamped row d^2

    const int tid = threadIdx.x;
    const int lane = tid & 31;
    const int wid = tid >> 5;                 // 0..7
    const int jb = blockIdx.x * CW;           // first column of tile
    const int ob = blockIdx.y * OROWS;        // first output row of tile

    // -------- Phase A: 14 scan rows over 8 warps (2 rounds) ----------------
    #pragma unroll
    for (int s = 0; s < 2; s++) {
        const int r = wid + s * 8;
        if (r < SROWS) {                      // warp-uniform
            const int srow = ob - FHALO + r;  // global image row
            const bool vrow = (srow >= 0) && (srow < H);

            unsigned mk = 0u;
            if (vrow) {
                const float4* __restrict__ i4 =
                    (const float4*)(img + srow * W + jb) + lane * 2;
                const float4 v0 = i4[0], v1 = i4[1];
                if (v0.x == 0.0f) mk |= 1u;
                if (v0.y == 0.0f) mk |= 2u;
                if (v0.z == 0.0f) mk |= 4u;
                if (v0.w == 0.0f) mk |= 8u;
                if (v1.x == 0.0f) mk |= 16u;
                if (v1.y == 0.0f) mk |= 32u;
                if (v1.z == 0.0f) mk |= 64u;
                if (v1.w == 0.0f) mk |= 128u;
            }

            // Neighbor bits (all lanes execute shuffles).
            unsigned p3 = __shfl_up_sync(0xffffffffu, mk, 1) >> 5;
            unsigned n3 = __shfl_down_sync(0xffffffffu, mk, 1) & 7u;

            // Tile-edge bits from gmem (left: cols jb-3..jb-1, right: jb+CW..+2).
            if (lane == 0) {
                p3 = 0u;
                if (vrow && jb > 0) {
                    const float* e = img + srow * W + jb - 3;
                    if (e[0] == 0.0f) p3 |= 1u;
                    if (e[1] == 0.0f) p3 |= 2u;
                    if (e[2] == 0.0f) p3 |= 4u;
                }
            }
            if (lane == 31) {
                n3 = 0u;
                if (vrow && jb + CW < W) {
                    const float* e = img + srow * W + jb + CW;
                    if (e[0] == 0.0f) n3 |= 1u;
                    if (e[1] == 0.0f) n3 |= 2u;
                    if (e[2] == 0.0f) n3 |= 4u;
                }
            }

            // ext bit k = zero flag of pixel (segment base - 3 + k), k=0..13
            const unsigned ext = p3 | (mk << 3) | (n3 << 11);

            float dv[8];
            #pragma unroll
            for (int p = 0; p < 8; p++) {
                const unsigned wb = (ext >> p) & 0x7Fu;  // bit 3 = center px
                float d2 = 16.0f;                        // d >= 4 (clamped)
                if (wb & 0x41u) d2 = 9.0f;               // d = 3
                if (wb & 0x22u) d2 = 4.0f;               // d = 2
                if (wb & 0x14u) d2 = 1.0f;               // d = 1
                if (wb & 0x08u) d2 = 0.0f;               // d = 0
                dv[p] = d2;
            }
            *(float4*)&sd[r * CW + lane * 8]     =
                make_float4(dv[0], dv[1], dv[2], dv[3]);
            *(float4*)&sd[r * CW + lane * 8 + 4] =
                make_float4(dv[4], dv[5], dv[6], dv[7]);
        }
    }
    __syncthreads();

    // -------- Phase B: column parabola window (1 column per thread) --------
    float wv[SROWS];
    #pragma unroll
    for (int k = 0; k < SROWS; k++) wv[k] = sd[k * CW + tid];

    float m[OROWS];
    #pragma unroll
    for (int u = 0; u < OROWS; u++) m[u] = wv[u + FHALO];   // d_i = 0 tap
    #pragma unroll
    for (int d = 1; d <= FHALO; d++) {
        const float dd = (float)(d * d);
        #pragma unroll
        for (int u = 0; u < OROWS; u++) {
            m[u] = fminf(m[u], wv[u + FHALO - d] + dd);
            m[u] = fminf(m[u], wv[u + FHALO + d] + dd);
        }
    }

    // m <= 9 => exact: clamped taps and |d_i| >= 4 taps are all >= 16 > 9.
    const int j = jb + tid;
    #pragma unroll
    for (int u = 0; u < OROWS; u++) {
        float mv = m[u];
        if (mv > 9.0f) mv = brute_force_d2(img, ob + u, j);
        out[(ob + u) * W + j] = sqrt_approx(mv);
    }
}

// ---------------------------------------------------------------------------
extern "C" void kernel_launch(void* const* d_in, const int* in_sizes, int n_in,
                              void* d_out, int out_size) {
    const float* img = (const float*)d_in[0];
    float* out = (float*)d_out;

    dim3 grid(W / CW, H / OROWS);     // (4, 128) = 512 CTAs
    edt_fused_kernel<<<grid, 256>>>(img, out);
}